// round 16
// baseline (speedup 1.0000x reference)
#include <cuda_runtime.h>
#include <cuda_bf16.h>
#include <cstdint>
#include <math.h>

#define N_ROWS 16384
#define NF     39
#define VP1    100001
#define NE     16
#define ND     624   // F*E
#define NH     400
#define EPS    1e-5f

#define KP1 640   // ND padded to multiple of 32
#define NC1 20    // KP1/32
#define KP2 416   // NH padded (13 chunks)
#define NC2 13    // KP2/32

// ---------------- scratch (static __device__, no allocations) ----------------
__device__ __align__(16) __nv_bfloat16 g_A1h[(size_t)N_ROWS * KP1];
__device__ __align__(16) __nv_bfloat16 g_A1l[(size_t)N_ROWS * KP1];
__device__ __align__(16) __nv_bfloat16 g_Z1h[(size_t)N_ROWS * KP2];
__device__ __align__(16) __nv_bfloat16 g_Z1l[(size_t)N_ROWS * KP2];
__device__ __align__(16) __nv_bfloat16 g_W1h[(size_t)NH * KP1];
__device__ __align__(16) __nv_bfloat16 g_W1l[(size_t)NH * KP1];
__device__ __align__(16) __nv_bfloat16 g_W2h[(size_t)NH * KP2];
__device__ __align__(16) __nv_bfloat16 g_W2l[(size_t)NH * KP2];
__device__ float g_stats[4 * NH];
__device__ float g_c2   [NH];
__device__ __align__(16) float g_w [KP2 + 1];   // w[0..KP2), D at [KP2]

// ---------------- helpers ----------------
__device__ __forceinline__ uint32_t smem_u32(const void* p) {
    uint32_t a;
    asm("{ .reg .u64 t; cvta.to.shared.u64 t, %1; cvt.u32.u64 %0, t; }"
        : "=r"(a) : "l"(p));
    return a;
}

__device__ __forceinline__ void cpa16(uint32_t dst, const void* src) {
    asm volatile("cp.async.cg.shared.global [%0], [%1], 16;"
                 :: "r"(dst), "l"(src));
}

#define CP_COMMIT() asm volatile("cp.async.commit_group;" ::: "memory")
#define CP_WAIT1()  asm volatile("cp.async.wait_group 1;" ::: "memory")
#define CP_WAIT0()  asm volatile("cp.async.wait_group 0;" ::: "memory")

#define LDSM_X4(r, addr) \
    asm volatile("ldmatrix.sync.aligned.m8n8.x4.shared.b16 {%0,%1,%2,%3}, [%4];" \
        : "=r"((r)[0]), "=r"((r)[1]), "=r"((r)[2]), "=r"((r)[3]) : "r"(addr))

#define MMA16816(d, a, b0, b1) \
    asm volatile("mma.sync.aligned.m16n8k16.row.col.f32.bf16.bf16.f32 " \
        "{%0,%1,%2,%3}, {%4,%5,%6,%7}, {%8,%9}, {%0,%1,%2,%3};" \
        : "+f"((d)[0]), "+f"((d)[1]), "+f"((d)[2]), "+f"((d)[3]) \
        : "r"((a)[0]), "r"((a)[1]), "r"((a)[2]), "r"((a)[3]), \
          "r"(b0), "r"(b1))

__device__ __forceinline__ void split_bf16(float x, __nv_bfloat16& h, __nv_bfloat16& l) {
    h = __float2bfloat16(x);
    l = __float2bfloat16(x - __bfloat162float(h));
}

// ---------------- embedding gather + e1 + FM2 + split deep (+stats zero) -----
__global__ void __launch_bounds__(128) embed_kernel(
    const int* __restrict__ xi, const float* __restrict__ xv,
    const float* __restrict__ emb1, const float* __restrict__ emb2,
    const float* __restrict__ bias,
    __nv_bfloat16* __restrict__ Ah, __nv_bfloat16* __restrict__ Al,
    float* __restrict__ out, float* __restrict__ stats)
{
    int n = blockIdx.x;
    int t = threadIdx.x;
    if (n == 0) {
        for (int i = t; i < 4 * NH; i += 128) stats[i] = 0.f;
    }
    __shared__ int   idx_s[NF];
    __shared__ float xv_s[NF];
    __shared__ __align__(16) float vals[ND];
    __shared__ float redw[4];

    if (t < NF) {
        idx_s[t] = xi[n * NF + t];
        xv_s[t]  = xv[n * NF + t];
    }
    __syncthreads();

    #pragma unroll
    for (int u = t; u < 156; u += 128) {
        int f = u >> 2, e4 = u & 3;
        const float4 v4 = *reinterpret_cast<const float4*>(
            emb2 + ((size_t)f * VP1 + idx_s[f]) * NE + e4 * 4);
        float s = xv_s[f];
        float v0 = v4.x * s, v1 = v4.y * s, v2 = v4.z * s, v3 = v4.w * s;
        *reinterpret_cast<float4*>(vals + u * 4) = make_float4(v0, v1, v2, v3);

        __nv_bfloat16 h0, h1, h2, h3, l0, l1, l2, l3;
        split_bf16(v0, h0, l0); split_bf16(v1, h1, l1);
        split_bf16(v2, h2, l2); split_bf16(v3, h3, l3);
        __nv_bfloat162 a01; a01.x = h0; a01.y = h1;
        __nv_bfloat162 a23; a23.x = h2; a23.y = h3;
        __nv_bfloat162 b01; b01.x = l0; b01.y = l1;
        __nv_bfloat162 b23; b23.x = l2; b23.y = l3;
        uint2 hp, lp;
        hp.x = *reinterpret_cast<uint32_t*>(&a01);
        hp.y = *reinterpret_cast<uint32_t*>(&a23);
        lp.x = *reinterpret_cast<uint32_t*>(&b01);
        lp.y = *reinterpret_cast<uint32_t*>(&b23);
        *reinterpret_cast<uint2*>(Ah + (size_t)n * KP1 + u * 4) = hp;
        *reinterpret_cast<uint2*>(Al + (size_t)n * KP1 + u * 4) = lp;
    }
    if (t >= 28 && t < 32) {
        uint2 z = make_uint2(0u, 0u);
        *reinterpret_cast<uint2*>(Ah + (size_t)n * KP1 + 624 + (t - 28) * 4) = z;
        *reinterpret_cast<uint2*>(Al + (size_t)n * KP1 + 624 + (t - 28) * 4) = z;
    }

    float contrib = 0.f;
    if (t < NF)
        contrib = emb1[(size_t)t * VP1 + idx_s[t]] * xv_s[t];
    __syncthreads();

    if (t < NE) {
        float s = 0.f, sq = 0.f;
        #pragma unroll
        for (int f = 0; f < NF; f++) {
            float v = vals[f * NE + t];
            s += v; sq += v * v;
        }
        contrib += 0.5f * (s * s - sq);
    }

    #pragma unroll
    for (int off = 16; off > 0; off >>= 1)
        contrib += __shfl_down_sync(0xFFFFFFFF, contrib, off);
    int lane = t & 31, w = t >> 5;
    if (lane == 0) redw[w] = contrib;
    __syncthreads();
    if (t == 0)
        out[n] = redw[0] + redw[1] + bias[0];
}

// ---------------- W1 repack: transpose + split ----------------
__global__ void repackW_kernel(const float* __restrict__ W,
                               __nv_bfloat16* __restrict__ Wh,
                               __nv_bfloat16* __restrict__ Wl,
                               int K, int Kpad)
{
    size_t idx = (size_t)blockIdx.x * blockDim.x + threadIdx.x;
    if (idx >= (size_t)NH * Kpad) return;
    int k = (int)(idx % Kpad);
    int n = (int)(idx / Kpad);
    float v = (k < K) ? W[(size_t)k * NH + n] : 0.f;
    __nv_bfloat16 h, l; split_bf16(v, h, l);
    Wh[idx] = h; Wl[idx] = l;
}

// ---------------- fused BN1-fold + W2 repack + c2 vector ----------------
__global__ void __launch_bounds__(256) repackW2c_kernel(
    const float* __restrict__ W2, const float* __restrict__ b2,
    const float* __restrict__ stats,
    const float* __restrict__ g1, const float* __restrict__ be1,
    __nv_bfloat16* __restrict__ Wh, __nv_bfloat16* __restrict__ Wl,
    float* __restrict__ c2)
{
    __shared__ float a_s[NH];
    __shared__ float sh_s[NH];
    __shared__ float redw[8];
    int n = blockIdx.x;
    int t = threadIdx.x;
    for (int k = t; k < NH; k += 256) {
        float mean = stats[k] * (1.f / N_ROWS);
        float var  = stats[NH + k] * (1.f / N_ROWS) - mean * mean;
        float a = g1[k] * rsqrtf(var + EPS);
        a_s[k]  = a;
        sh_s[k] = be1[k] - a * mean;
    }
    __syncthreads();

    float partial = 0.f;
    for (int k = t; k < KP2; k += 256) {
        float w = 0.f, a = 0.f, sh = 0.f;
        if (k < NH) {
            w  = W2[(size_t)k * NH + n];
            a  = a_s[k];
            sh = sh_s[k];
        }
        __nv_bfloat16 h, l; split_bf16(a * w, h, l);
        Wh[(size_t)n * KP2 + k] = h;
        Wl[(size_t)n * KP2 + k] = l;
        partial += sh * w;
    }
    #pragma unroll
    for (int off = 16; off > 0; off >>= 1)
        partial += __shfl_down_sync(0xFFFFFFFF, partial, off);
    int lane = t & 31, w = t >> 5;
    if (lane == 0) redw[w] = partial;
    __syncthreads();
    if (t == 0) {
        float s = 0.f;
        #pragma unroll
        for (int i = 0; i < 8; i++) s += redw[i];
        c2[n] = s + b2[n];
    }
}

// ---------------- HMMA GEMM: C = (Ah+Al) @ (Bh+Bl)^T + bias ------------------
// BM=128, BN=80, BK=32; 128 threads = 4 warps; warp tile 32x80 (2 m16 tiles).
// Runtime chunk loop, 2-stage cp.async, 66.5KB SMEM -> 3 CTAs/SM.
// Early prefetch after the ks=1 LDSM batch. [R14 proven configuration]
// EPI=0: store split bf16 Z + stats. EPI=1: stats ONLY (no Z materialized).
template<int EPI>
__global__ void __launch_bounds__(128, 3) hmma_gemm_kernel(
    const __nv_bfloat16* __restrict__ Ah, const __nv_bfloat16* __restrict__ Al,
    const __nv_bfloat16* __restrict__ Bh, const __nv_bfloat16* __restrict__ Bl,
    const float* __restrict__ bias,
    __nv_bfloat16* __restrict__ Zh, __nv_bfloat16* __restrict__ Zl,
    float* __restrict__ gsum, float* __restrict__ gsq,
    int Kpad, int nchunk)
{
    extern __shared__ __nv_bfloat16 smem[];
    const int BUF = 16640;                      // bf16 per buffer
    const uint32_t sbase = smem_u32(smem);

    int tid = threadIdx.x;
    int wid = tid >> 5, lane = tid & 31;
    int n0 = blockIdx.x * 80;
    int m0 = blockIdx.y * 128;

    float acc[20][4];
    #pragma unroll
    for (int i = 0; i < 20; i++)
        #pragma unroll
        for (int j = 0; j < 4; j++) acc[i][j] = 0.f;

    const uint32_t aoff0 = (uint32_t)((wid * 32 + (lane & 15)) * 40
                                      + (lane >> 4) * 8) * 2;
    const uint32_t aoff1 = aoff0 + (uint32_t)(16 * 40) * 2;
    const int rowB = (lane & 7) + ((lane >> 3) & 1) * 8;
    const uint32_t boff = (uint32_t)(10240 + rowB * 40 + (lane >> 4) * 8) * 2;

    auto load_chunk = [&](int buf, int kc) {
        uint32_t sb = sbase + (uint32_t)buf * BUF * 2;
        int k0 = kc * 32;
        #pragma unroll
        for (int l = 0; l < 4; l++) {
            int i = tid + l * 128;
            int row = i >> 2, c = (i & 3) * 8;
            size_t go = (size_t)(m0 + row) * Kpad + k0 + c;
            uint32_t d = sb + (uint32_t)(row * 40 + c) * 2;
            cpa16(d, Ah + go);
            cpa16(d + 5120 * 2, Al + go);
        }
        #pragma unroll
        for (int l = 0; l < 3; l++) {
            int i = tid + l * 128;
            if (i < 320) {
                int row = i >> 2, c = (i & 3) * 8;
                size_t go = (size_t)(n0 + row) * Kpad + k0 + c;
                uint32_t d = sb + (uint32_t)(10240 + row * 40 + c) * 2;
                cpa16(d, Bh + go);
                cpa16(d + 3200 * 2, Bl + go);
            }
        }
        CP_COMMIT();
    };

    load_chunk(0, 0);
    if (nchunk > 1) load_chunk(1, 1);

    for (int kc = 0; kc < nchunk; kc++) {
        if (kc + 1 < nchunk) CP_WAIT1(); else CP_WAIT0();
        __syncthreads();

        uint32_t sb = sbase + (uint32_t)(kc & 1) * BUF * 2;

        // ---- ks = 0 ----
        {
            uint32_t ah0[4], ah1[4], al0[4], al1[4];
            LDSM_X4(ah0, sb + aoff0);
            LDSM_X4(ah1, sb + aoff1);
            LDSM_X4(al0, sb + aoff0 + 5120 * 2);
            LDSM_X4(al1, sb + aoff1 + 5120 * 2);
            uint32_t bbase = sb + boff;
            uint32_t bh[5][4], bl[5][4];
            #pragma unroll
            for (int g = 0; g < 5; g++)
                LDSM_X4(bh[g], bbase + (uint32_t)(g * 16 * 40) * 2);
            #pragma unroll
            for (int g = 0; g < 5; g++)
                LDSM_X4(bl[g], bbase + (uint32_t)(3200 + g * 16 * 40) * 2);

            #pragma unroll
            for (int g = 0; g < 5; g++) {
                MMA16816(acc[2 * g],          ah0, bh[g][0], bh[g][2]);
                MMA16816(acc[2 * g + 1],      ah0, bh[g][1], bh[g][3]);
                MMA16816(acc[10 + 2 * g],     ah1, bh[g][0], bh[g][2]);
                MMA16816(acc[10 + 2 * g + 1], ah1, bh[g][1], bh[g][3]);
            }
            #pragma unroll
            for (int g = 0; g < 5; g++) {
                MMA16816(acc[2 * g],          al0, bh[g][0], bh[g][2]);
                MMA16816(acc[2 * g + 1],      al0, bh[g][1], bh[g][3]);
                MMA16816(acc[10 + 2 * g],     al1, bh[g][0], bh[g][2]);
                MMA16816(acc[10 + 2 * g + 1], al1, bh[g][1], bh[g][3]);
            }
            #pragma unroll
            for (int g = 0; g < 5; g++) {
                MMA16816(acc[2 * g],          ah0, bl[g][0], bl[g][2]);
                MMA16816(acc[2 * g + 1],      ah0, bl[g][1], bl[g][3]);
                MMA16816(acc[10 + 2 * g],     ah1, bl[g][0], bl[g][2]);
                MMA16816(acc[10 + 2 * g + 1], ah1, bl[g][1], bl[g][3]);
            }
        }

        // ---- ks = 1: LDSM first, then prefetch, then MMA ----
        {
            const uint32_t kso = 16 * 2;
            uint32_t ah0[4], ah1[4], al0[4], al1[4];
            LDSM_X4(ah0, sb + aoff0 + kso);
            LDSM_X4(ah1, sb + aoff1 + kso);
            LDSM_X4(al0, sb + aoff0 + kso + 5120 * 2);
            LDSM_X4(al1, sb + aoff1 + kso + 5120 * 2);
            uint32_t bbase = sb + boff + kso;
            uint32_t bh[5][4], bl[5][4];
            #pragma unroll
            for (int g = 0; g < 5; g++)
                LDSM_X4(bh[g], bbase + (uint32_t)(g * 16 * 40) * 2);
            #pragma unroll
            for (int g = 0; g < 5; g++)
                LDSM_X4(bl[g], bbase + (uint32_t)(3200 + g * 16 * 40) * 2);

            if (kc + 2 < nchunk) {
                __syncthreads();
                load_chunk(kc & 1, kc + 2);
            }

            #pragma unroll
            for (int g = 0; g < 5; g++) {
                MMA16816(acc[2 * g],          ah0, bh[g][0], bh[g][2]);
                MMA16816(acc[2 * g + 1],      ah0, bh[g][1], bh[g][3]);
                MMA16816(acc[10 + 2 * g],     ah1, bh[g][0], bh[g][2]);
                MMA16816(acc[10 + 2 * g + 1], ah1, bh[g][1], bh[g][3]);
            }
            #pragma unroll
            for (int g = 0; g < 5; g++) {
                MMA16816(acc[2 * g],          al0, bh[g][0], bh[g][2]);
                MMA16816(acc[2 * g + 1],      al0, bh[g][1], bh[g][3]);
                MMA16816(acc[10 + 2 * g],     al1, bh[g][0], bh[g][2]);
                MMA16816(acc[10 + 2 * g + 1], al1, bh[g][1], bh[g][3]);
            }
            #pragma unroll
            for (int g = 0; g < 5; g++) {
                MMA16816(acc[2 * g],          ah0, bl[g][0], bl[g][2]);
                MMA16816(acc[2 * g + 1],      ah0, bl[g][1], bl[g][3]);
                MMA16816(acc[10 + 2 * g],     ah1, bl[g][0], bl[g][2]);
                MMA16816(acc[10 + 2 * g + 1], ah1, bl[g][1], bl[g][3]);
            }
        }
    }

    // ---- epilogue ----
    __syncthreads();
    float* ssum = reinterpret_cast<float*>(smem);       // 80
    float* ssq  = ssum + 80;                            // 80
    for (int i = tid; i < 160; i += 128) ssum[i] = 0.f;
    __syncthreads();

    int cb = n0 + (lane & 3) * 2;
    #pragma unroll
    for (int mi = 0; mi < 2; mi++) {
        int r0 = m0 + wid * 32 + mi * 16 + (lane >> 2);
        #pragma unroll
        for (int nt = 0; nt < 10; nt++) {
            float* a4 = acc[mi * 10 + nt];
            int n = cb + nt * 8;
            float bz0 = bias[n], bz1 = bias[n + 1];
            float v00 = a4[0] + bz0, v01 = a4[1] + bz1;
            float v10 = a4[2] + bz0, v11 = a4[3] + bz1;

            if (EPI == 0) {
                __nv_bfloat162 h0, l0, h1, l1;
                split_bf16(v00, h0.x, l0.x); split_bf16(v01, h0.y, l0.y);
                split_bf16(v10, h1.x, l1.x); split_bf16(v11, h1.y, l1.y);
                *reinterpret_cast<__nv_bfloat162*>(Zh + (size_t)r0 * KP2 + n) = h0;
                *reinterpret_cast<__nv_bfloat162*>(Zl + (size_t)r0 * KP2 + n) = l0;
                *reinterpret_cast<__nv_bfloat162*>(Zh + (size_t)(r0 + 8) * KP2 + n) = h1;
                *reinterpret_cast<__nv_bfloat162*>(Zl + (size_t)(r0 + 8) * KP2 + n) = l1;
            }
            // EPI==1: stats only, no store

            float s0 = v00 + v10, q0 = v00 * v00 + v10 * v10;
            float s1 = v01 + v11, q1 = v01 * v01 + v11 * v11;
            #pragma unroll
            for (int off = 16; off >= 4; off >>= 1) {
                s0 += __shfl_down_sync(0xFFFFFFFF, s0, off);
                q0 += __shfl_down_sync(0xFFFFFFFF, q0, off);
                s1 += __shfl_down_sync(0xFFFFFFFF, s1, off);
                q1 += __shfl_down_sync(0xFFFFFFFF, q1, off);
            }
            if (lane < 4) {
                int lc = lane * 2 + nt * 8;
                atomicAdd(&ssum[lc],     s0);
                atomicAdd(&ssum[lc + 1], s1);
                atomicAdd(&ssq[lc],      q0);
                atomicAdd(&ssq[lc + 1],  q1);
            }
        }
    }

    // zero-pad columns [400, 416) of the split output
    if (EPI == 0 && n0 == 320) {
        for (int i = tid; i < 512; i += 128) {
            int row = i >> 2, q = i & 3;
            size_t off = (size_t)(m0 + row) * KP2 + 400 + q * 4;
            *reinterpret_cast<uint2*>(Zh + off) = make_uint2(0u, 0u);
            *reinterpret_cast<uint2*>(Zl + off) = make_uint2(0u, 0u);
        }
    }

    __syncthreads();
    for (int i = tid; i < 80; i += 128) {
        atomicAdd(&gsum[n0 + i], ssum[i]);
        atomicAdd(&gsq[n0 + i],  ssq[i]);
    }
}

// ---------------- w-vector build: w[k] = sum_j a2_j * W2'[j,k]; D scalar -----
// grid = 13 blocks (32 k-columns each), 256 threads (8 j-slices of 50).
__global__ void __launch_bounds__(256) wvec_kernel(
    const __nv_bfloat16* __restrict__ W2h, const __nv_bfloat16* __restrict__ W2l,
    const float* __restrict__ c2, const float* __restrict__ stats,
    const float* __restrict__ g2, const float* __restrict__ be2,
    float* __restrict__ wD)
{
    __shared__ float a_s[NH];
    __shared__ float part[8][32];
    __shared__ float redD[8];
    int t = threadIdx.x;
    int lane32 = t & 31, slice = t >> 5;

    float dpart = 0.f;
    for (int j = t; j < NH; j += 256) {
        float mean = stats[2 * NH + j] * (1.f / N_ROWS);
        float var  = stats[3 * NH + j] * (1.f / N_ROWS) - mean * mean;
        float a = g2[j] * rsqrtf(var + EPS);
        a_s[j] = a;
        dpart += (be2[j] - a * mean) + a * c2[j];
    }
    // D: reduce dpart (only block 0 writes)
    #pragma unroll
    for (int off = 16; off > 0; off >>= 1)
        dpart += __shfl_down_sync(0xFFFFFFFF, dpart, off);
    if (lane32 == 0) redD[slice] = dpart;
    __syncthreads();
    if (t == 0 && blockIdx.x == 0) {
        float s = 0.f;
        #pragma unroll
        for (int i = 0; i < 8; i++) s += redD[i];
        wD[KP2] = s;
    }

    int k = blockIdx.x * 32 + lane32;
    float acc = 0.f;
    for (int j = slice * 50; j < slice * 50 + 50; j++)
        acc += a_s[j] * (__bfloat162float(W2h[(size_t)j * KP2 + k])
                       + __bfloat162float(W2l[(size_t)j * KP2 + k]));
    part[slice][lane32] = acc;
    __syncthreads();
    if (slice == 0) {
        float s = 0.f;
        #pragma unroll
        for (int i = 0; i < 8; i++) s += part[i][lane32];
        wD[k] = s;
    }
}

// ---------------- final GEMV: out[n] += sum_k (Z1h+Z1l)[n,k]*w[k] + D --------
__global__ void __launch_bounds__(256) rowdot_kernel(
    const __nv_bfloat16* __restrict__ Zh, const __nv_bfloat16* __restrict__ Zl,
    const float* __restrict__ wD, float* __restrict__ out)
{
    __shared__ float w_s[KP2];
    __shared__ float Ds;
    int t = threadIdx.x;
    for (int k = t; k < KP2; k += 256) w_s[k] = wD[k];
    if (t == 0) Ds = wD[KP2];
    __syncthreads();

    int lane = t & 31, w = t >> 5;
    int row = blockIdx.x * 8 + w;
    const __nv_bfloat162* zh2 = reinterpret_cast<const __nv_bfloat162*>(
        Zh + (size_t)row * KP2);
    const __nv_bfloat162* zl2 = reinterpret_cast<const __nv_bfloat162*>(
        Zl + (size_t)row * KP2);
    float acc = 0.f;
    for (int p = lane; p < KP2 / 2; p += 32) {
        __nv_bfloat162 h2 = zh2[p];
        __nv_bfloat162 l2 = zl2[p];
        float z0 = __bfloat162float(h2.x) + __bfloat162float(l2.x);
        float z1 = __bfloat162float(h2.y) + __bfloat162float(l2.y);
        acc += z0 * w_s[2 * p] + z1 * w_s[2 * p + 1];
    }
    #pragma unroll
    for (int off = 16; off > 0; off >>= 1)
        acc += __shfl_down_sync(0xFFFFFFFF, acc, off);
    if (lane == 0)
        out[row] += acc + Ds;
}

// ---------------- launch ----------------
extern "C" void kernel_launch(void* const* d_in, const int* in_sizes, int n_in,
                              void* d_out, int out_size)
{
    const int*   xi   = (const int*)  d_in[0];
    const float* xv   = (const float*)d_in[1];
    const float* emb1 = (const float*)d_in[2];
    const float* emb2 = (const float*)d_in[3];
    const float* W1   = (const float*)d_in[4];
    const float* b1   = (const float*)d_in[5];
    const float* g1   = (const float*)d_in[6];
    const float* be1  = (const float*)d_in[7];
    const float* W2   = (const float*)d_in[8];
    const float* b2   = (const float*)d_in[9];
    const float* g2   = (const float*)d_in[10];
    const float* be2  = (const float*)d_in[11];
    const float* bias = (const float*)d_in[12];
    float* out = (float*)d_out;

    __nv_bfloat16 *A1h, *A1l, *Z1h, *Z1l, *W1h, *W1l, *W2h, *W2l;
    float *stats, *c2, *wD;
    cudaGetSymbolAddress((void**)&A1h, g_A1h);
    cudaGetSymbolAddress((void**)&A1l, g_A1l);
    cudaGetSymbolAddress((void**)&Z1h, g_Z1h);
    cudaGetSymbolAddress((void**)&Z1l, g_Z1l);
    cudaGetSymbolAddress((void**)&W1h, g_W1h);
    cudaGetSymbolAddress((void**)&W1l, g_W1l);
    cudaGetSymbolAddress((void**)&W2h, g_W2h);
    cudaGetSymbolAddress((void**)&W2l, g_W2l);
    cudaGetSymbolAddress((void**)&stats, g_stats);
    cudaGetSymbolAddress((void**)&c2,    g_c2);
    cudaGetSymbolAddress((void**)&wD,    g_w);

    const int SMEM_BYTES = 2 * 16640 * 2;   // 66560
    cudaFuncSetAttribute(hmma_gemm_kernel<0>,
                         cudaFuncAttributeMaxDynamicSharedMemorySize, SMEM_BYTES);
    cudaFuncSetAttribute(hmma_gemm_kernel<1>,
                         cudaFuncAttributeMaxDynamicSharedMemorySize, SMEM_BYTES);

    embed_kernel<<<N_ROWS, 128>>>(xi, xv, emb1, emb2, bias, A1h, A1l, out, stats);
    repackW_kernel<<<((size_t)NH * KP1 + 255) / 256, 256>>>(W1, W1h, W1l, ND, KP1);

    dim3 ggrid(5, N_ROWS / 128);
    hmma_gemm_kernel<0><<<ggrid, 128, SMEM_BYTES>>>(
        A1h, A1l, W1h, W1l, b1, Z1h, Z1l,
        stats, stats + NH, KP1, NC1);

    repackW2c_kernel<<<NH, 256>>>(W2, b2, stats, g1, be1, W2h, W2l, c2);

    hmma_gemm_kernel<1><<<ggrid, 128, SMEM_BYTES>>>(
        Z1h, Z1l, W2h, W2l, c2, nullptr, nullptr,
        stats + 2 * NH, stats + 3 * NH, KP2, NC2);

    wvec_kernel<<<13, 256>>>(W2h, W2l, c2, stats, g2, be2, wD);
    rowdot_kernel<<<N_ROWS / 8, 256>>>(Z1h, Z1l, wD, out);
}

// round 17
// speedup vs baseline: 1.0092x; 1.0092x over previous
#include <cuda_runtime.h>
#include <cuda_bf16.h>
#include <cstdint>
#include <math.h>

#define N_ROWS 16384
#define NF     39
#define VP1    100001
#define NE     16
#define ND     624   // F*E
#define NH     400
#define EPS    1e-5f

#define KP1 640   // ND padded to multiple of 32
#define NC1 20    // KP1/32
#define KP2 416   // NH padded (13 chunks)
#define NC2 13    // KP2/32

// ---------------- scratch (static __device__, no allocations) ----------------
__device__ __align__(16) __nv_bfloat16 g_A1h[(size_t)N_ROWS * KP1];
__device__ __align__(16) __nv_bfloat16 g_A1l[(size_t)N_ROWS * KP1];
__device__ __align__(16) __nv_bfloat16 g_Z1h[(size_t)N_ROWS * KP2];
__device__ __align__(16) __nv_bfloat16 g_Z1l[(size_t)N_ROWS * KP2];
__device__ __align__(16) __nv_bfloat16 g_W1h[(size_t)NH * KP1];
__device__ __align__(16) __nv_bfloat16 g_W1l[(size_t)NH * KP1];
__device__ __align__(16) __nv_bfloat16 g_W2h[(size_t)NH * KP2];
__device__ __align__(16) __nv_bfloat16 g_W2l[(size_t)NH * KP2];
__device__ float g_stats[4 * NH];
__device__ float g_c2   [NH];
__device__ __align__(16) float g_w [KP2 + 1];   // w[0..KP2), D at [KP2]

// ---------------- helpers ----------------
__device__ __forceinline__ uint32_t smem_u32(const void* p) {
    uint32_t a;
    asm("{ .reg .u64 t; cvta.to.shared.u64 t, %1; cvt.u32.u64 %0, t; }"
        : "=r"(a) : "l"(p));
    return a;
}

__device__ __forceinline__ void cpa16(uint32_t dst, const void* src) {
    asm volatile("cp.async.cg.shared.global [%0], [%1], 16;"
                 :: "r"(dst), "l"(src));
}

#define CP_COMMIT() asm volatile("cp.async.commit_group;" ::: "memory")
#define CP_WAIT1()  asm volatile("cp.async.wait_group 1;" ::: "memory")
#define CP_WAIT0()  asm volatile("cp.async.wait_group 0;" ::: "memory")

#define LDSM_X4(r, addr) \
    asm volatile("ldmatrix.sync.aligned.m8n8.x4.shared.b16 {%0,%1,%2,%3}, [%4];" \
        : "=r"((r)[0]), "=r"((r)[1]), "=r"((r)[2]), "=r"((r)[3]) : "r"(addr))

#define MMA16816(d, a, b0, b1) \
    asm volatile("mma.sync.aligned.m16n8k16.row.col.f32.bf16.bf16.f32 " \
        "{%0,%1,%2,%3}, {%4,%5,%6,%7}, {%8,%9}, {%0,%1,%2,%3};" \
        : "+f"((d)[0]), "+f"((d)[1]), "+f"((d)[2]), "+f"((d)[3]) \
        : "r"((a)[0]), "r"((a)[1]), "r"((a)[2]), "r"((a)[3]), \
          "r"(b0), "r"(b1))

__device__ __forceinline__ void split_bf16(float x, __nv_bfloat16& h, __nv_bfloat16& l) {
    h = __float2bfloat16(x);
    l = __float2bfloat16(x - __bfloat162float(h));
}

// ---------------- embedding gather + e1 + FM2 + split deep -------------------
// Also: stats zero (block 0) and W1 repack distributed over blocks 0..1999.
__global__ void __launch_bounds__(128) embed_kernel(
    const int* __restrict__ xi, const float* __restrict__ xv,
    const float* __restrict__ emb1, const float* __restrict__ emb2,
    const float* __restrict__ bias, const float* __restrict__ W1,
    __nv_bfloat16* __restrict__ Ah, __nv_bfloat16* __restrict__ Al,
    __nv_bfloat16* __restrict__ W1h, __nv_bfloat16* __restrict__ W1l,
    float* __restrict__ out, float* __restrict__ stats)
{
    int n = blockIdx.x;
    int t = threadIdx.x;
    if (n == 0) {
        for (int i = t; i < 4 * NH; i += 128) stats[i] = 0.f;
    }
    // distributed W1 repack: NH*KP1 = 256000 elements over blocks 0..1999
    {
        int idx = n * 128 + t;
        if (idx < NH * KP1) {
            int k  = idx % KP1;
            int nn = idx / KP1;
            float v = (k < ND) ? W1[(size_t)k * NH + nn] : 0.f;
            __nv_bfloat16 h, l; split_bf16(v, h, l);
            W1h[idx] = h; W1l[idx] = l;
        }
    }

    __shared__ int   idx_s[NF];
    __shared__ float xv_s[NF];
    __shared__ __align__(16) float vals[ND];
    __shared__ float redw[4];

    if (t < NF) {
        idx_s[t] = xi[n * NF + t];
        xv_s[t]  = xv[n * NF + t];
    }
    __syncthreads();

    #pragma unroll
    for (int u = t; u < 156; u += 128) {
        int f = u >> 2, e4 = u & 3;
        const float4 v4 = *reinterpret_cast<const float4*>(
            emb2 + ((size_t)f * VP1 + idx_s[f]) * NE + e4 * 4);
        float s = xv_s[f];
        float v0 = v4.x * s, v1 = v4.y * s, v2 = v4.z * s, v3 = v4.w * s;
        *reinterpret_cast<float4*>(vals + u * 4) = make_float4(v0, v1, v2, v3);

        __nv_bfloat16 h0, h1, h2, h3, l0, l1, l2, l3;
        split_bf16(v0, h0, l0); split_bf16(v1, h1, l1);
        split_bf16(v2, h2, l2); split_bf16(v3, h3, l3);
        __nv_bfloat162 a01; a01.x = h0; a01.y = h1;
        __nv_bfloat162 a23; a23.x = h2; a23.y = h3;
        __nv_bfloat162 b01; b01.x = l0; b01.y = l1;
        __nv_bfloat162 b23; b23.x = l2; b23.y = l3;
        uint2 hp, lp;
        hp.x = *reinterpret_cast<uint32_t*>(&a01);
        hp.y = *reinterpret_cast<uint32_t*>(&a23);
        lp.x = *reinterpret_cast<uint32_t*>(&b01);
        lp.y = *reinterpret_cast<uint32_t*>(&b23);
        *reinterpret_cast<uint2*>(Ah + (size_t)n * KP1 + u * 4) = hp;
        *reinterpret_cast<uint2*>(Al + (size_t)n * KP1 + u * 4) = lp;
    }
    if (t >= 28 && t < 32) {
        uint2 z = make_uint2(0u, 0u);
        *reinterpret_cast<uint2*>(Ah + (size_t)n * KP1 + 624 + (t - 28) * 4) = z;
        *reinterpret_cast<uint2*>(Al + (size_t)n * KP1 + 624 + (t - 28) * 4) = z;
    }

    float contrib = 0.f;
    if (t < NF)
        contrib = emb1[(size_t)t * VP1 + idx_s[t]] * xv_s[t];
    __syncthreads();

    if (t < NE) {
        float s = 0.f, sq = 0.f;
        #pragma unroll
        for (int f = 0; f < NF; f++) {
            float v = vals[f * NE + t];
            s += v; sq += v * v;
        }
        contrib += 0.5f * (s * s - sq);
    }

    #pragma unroll
    for (int off = 16; off > 0; off >>= 1)
        contrib += __shfl_down_sync(0xFFFFFFFF, contrib, off);
    int lane = t & 31, w = t >> 5;
    if (lane == 0) redw[w] = contrib;
    __syncthreads();
    if (t == 0)
        out[n] = redw[0] + redw[1] + bias[0];
}

// ---------------- fused BN1-fold + W2 repack + c2 vector ----------------
// 100 blocks x 4 columns: BN-fold computed once per block, amortized 4x.
__global__ void __launch_bounds__(256) repackW2c_kernel(
    const float* __restrict__ W2, const float* __restrict__ b2,
    const float* __restrict__ stats,
    const float* __restrict__ g1, const float* __restrict__ be1,
    __nv_bfloat16* __restrict__ Wh, __nv_bfloat16* __restrict__ Wl,
    float* __restrict__ c2)
{
    __shared__ float a_s[NH];
    __shared__ float sh_s[NH];
    __shared__ float redw[4][8];
    int n0 = blockIdx.x * 4;
    int t = threadIdx.x;
    for (int k = t; k < NH; k += 256) {
        float mean = stats[k] * (1.f / N_ROWS);
        float var  = stats[NH + k] * (1.f / N_ROWS) - mean * mean;
        float a = g1[k] * rsqrtf(var + EPS);
        a_s[k]  = a;
        sh_s[k] = be1[k] - a * mean;
    }
    __syncthreads();

    float part[4] = {0.f, 0.f, 0.f, 0.f};
    for (int k = t; k < KP2; k += 256) {
        float a = 0.f, sh = 0.f;
        if (k < NH) { a = a_s[k]; sh = sh_s[k]; }
        #pragma unroll
        for (int c = 0; c < 4; c++) {
            int n = n0 + c;
            float w = (k < NH) ? W2[(size_t)k * NH + n] : 0.f;
            __nv_bfloat16 h, l; split_bf16(a * w, h, l);
            Wh[(size_t)n * KP2 + k] = h;
            Wl[(size_t)n * KP2 + k] = l;
            part[c] += sh * w;
        }
    }
    int lane = t & 31, w = t >> 5;
    #pragma unroll
    for (int c = 0; c < 4; c++) {
        float p = part[c];
        #pragma unroll
        for (int off = 16; off > 0; off >>= 1)
            p += __shfl_down_sync(0xFFFFFFFF, p, off);
        if (lane == 0) redw[c][w] = p;
    }
    __syncthreads();
    if (t < 4) {
        float s = 0.f;
        #pragma unroll
        for (int i = 0; i < 8; i++) s += redw[t][i];
        c2[n0 + t] = s + b2[n0 + t];
    }
}

// ---------------- HMMA GEMM: C = (Ah+Al) @ (Bh+Bl)^T + bias ------------------
// BM=128, BN=80, BK=32; 128 threads = 4 warps; warp tile 32x80 (2 m16 tiles).
// Runtime chunk loop, 2-stage cp.async, 66.5KB SMEM -> 3 CTAs/SM.
// Early prefetch after the ks=1 LDSM batch. [R14 proven configuration]
// EPI=0: store split bf16 Z + stats. EPI=1: stats ONLY.
template<int EPI>
__global__ void __launch_bounds__(128, 3) hmma_gemm_kernel(
    const __nv_bfloat16* __restrict__ Ah, const __nv_bfloat16* __restrict__ Al,
    const __nv_bfloat16* __restrict__ Bh, const __nv_bfloat16* __restrict__ Bl,
    const float* __restrict__ bias,
    __nv_bfloat16* __restrict__ Zh, __nv_bfloat16* __restrict__ Zl,
    float* __restrict__ gsum, float* __restrict__ gsq,
    int Kpad, int nchunk)
{
    extern __shared__ __nv_bfloat16 smem[];
    const int BUF = 16640;                      // bf16 per buffer
    const uint32_t sbase = smem_u32(smem);

    int tid = threadIdx.x;
    int wid = tid >> 5, lane = tid & 31;
    int n0 = blockIdx.x * 80;
    int m0 = blockIdx.y * 128;

    float acc[20][4];
    #pragma unroll
    for (int i = 0; i < 20; i++)
        #pragma unroll
        for (int j = 0; j < 4; j++) acc[i][j] = 0.f;

    const uint32_t aoff0 = (uint32_t)((wid * 32 + (lane & 15)) * 40
                                      + (lane >> 4) * 8) * 2;
    const uint32_t aoff1 = aoff0 + (uint32_t)(16 * 40) * 2;
    const int rowB = (lane & 7) + ((lane >> 3) & 1) * 8;
    const uint32_t boff = (uint32_t)(10240 + rowB * 40 + (lane >> 4) * 8) * 2;

    auto load_chunk = [&](int buf, int kc) {
        uint32_t sb = sbase + (uint32_t)buf * BUF * 2;
        int k0 = kc * 32;
        #pragma unroll
        for (int l = 0; l < 4; l++) {
            int i = tid + l * 128;
            int row = i >> 2, c = (i & 3) * 8;
            size_t go = (size_t)(m0 + row) * Kpad + k0 + c;
            uint32_t d = sb + (uint32_t)(row * 40 + c) * 2;
            cpa16(d, Ah + go);
            cpa16(d + 5120 * 2, Al + go);
        }
        #pragma unroll
        for (int l = 0; l < 3; l++) {
            int i = tid + l * 128;
            if (i < 320) {
                int row = i >> 2, c = (i & 3) * 8;
                size_t go = (size_t)(n0 + row) * Kpad + k0 + c;
                uint32_t d = sb + (uint32_t)(10240 + row * 40 + c) * 2;
                cpa16(d, Bh + go);
                cpa16(d + 3200 * 2, Bl + go);
            }
        }
        CP_COMMIT();
    };

    load_chunk(0, 0);
    if (nchunk > 1) load_chunk(1, 1);

    for (int kc = 0; kc < nchunk; kc++) {
        if (kc + 1 < nchunk) CP_WAIT1(); else CP_WAIT0();
        __syncthreads();

        uint32_t sb = sbase + (uint32_t)(kc & 1) * BUF * 2;

        // ---- ks = 0 ----
        {
            uint32_t ah0[4], ah1[4], al0[4], al1[4];
            LDSM_X4(ah0, sb + aoff0);
            LDSM_X4(ah1, sb + aoff1);
            LDSM_X4(al0, sb + aoff0 + 5120 * 2);
            LDSM_X4(al1, sb + aoff1 + 5120 * 2);
            uint32_t bbase = sb + boff;
            uint32_t bh[5][4], bl[5][4];
            #pragma unroll
            for (int g = 0; g < 5; g++)
                LDSM_X4(bh[g], bbase + (uint32_t)(g * 16 * 40) * 2);
            #pragma unroll
            for (int g = 0; g < 5; g++)
                LDSM_X4(bl[g], bbase + (uint32_t)(3200 + g * 16 * 40) * 2);

            #pragma unroll
            for (int g = 0; g < 5; g++) {
                MMA16816(acc[2 * g],          ah0, bh[g][0], bh[g][2]);
                MMA16816(acc[2 * g + 1],      ah0, bh[g][1], bh[g][3]);
                MMA16816(acc[10 + 2 * g],     ah1, bh[g][0], bh[g][2]);
                MMA16816(acc[10 + 2 * g + 1], ah1, bh[g][1], bh[g][3]);
            }
            #pragma unroll
            for (int g = 0; g < 5; g++) {
                MMA16816(acc[2 * g],          al0, bh[g][0], bh[g][2]);
                MMA16816(acc[2 * g + 1],      al0, bh[g][1], bh[g][3]);
                MMA16816(acc[10 + 2 * g],     al1, bh[g][0], bh[g][2]);
                MMA16816(acc[10 + 2 * g + 1], al1, bh[g][1], bh[g][3]);
            }
            #pragma unroll
            for (int g = 0; g < 5; g++) {
                MMA16816(acc[2 * g],          ah0, bl[g][0], bl[g][2]);
                MMA16816(acc[2 * g + 1],      ah0, bl[g][1], bl[g][3]);
                MMA16816(acc[10 + 2 * g],     ah1, bl[g][0], bl[g][2]);
                MMA16816(acc[10 + 2 * g + 1], ah1, bl[g][1], bl[g][3]);
            }
        }

        // ---- ks = 1: LDSM first, then prefetch, then MMA ----
        {
            const uint32_t kso = 16 * 2;
            uint32_t ah0[4], ah1[4], al0[4], al1[4];
            LDSM_X4(ah0, sb + aoff0 + kso);
            LDSM_X4(ah1, sb + aoff1 + kso);
            LDSM_X4(al0, sb + aoff0 + kso + 5120 * 2);
            LDSM_X4(al1, sb + aoff1 + kso + 5120 * 2);
            uint32_t bbase = sb + boff + kso;
            uint32_t bh[5][4], bl[5][4];
            #pragma unroll
            for (int g = 0; g < 5; g++)
                LDSM_X4(bh[g], bbase + (uint32_t)(g * 16 * 40) * 2);
            #pragma unroll
            for (int g = 0; g < 5; g++)
                LDSM_X4(bl[g], bbase + (uint32_t)(3200 + g * 16 * 40) * 2);

            if (kc + 2 < nchunk) {
                __syncthreads();
                load_chunk(kc & 1, kc + 2);
            }

            #pragma unroll
            for (int g = 0; g < 5; g++) {
                MMA16816(acc[2 * g],          ah0, bh[g][0], bh[g][2]);
                MMA16816(acc[2 * g + 1],      ah0, bh[g][1], bh[g][3]);
                MMA16816(acc[10 + 2 * g],     ah1, bh[g][0], bh[g][2]);
                MMA16816(acc[10 + 2 * g + 1], ah1, bh[g][1], bh[g][3]);
            }
            #pragma unroll
            for (int g = 0; g < 5; g++) {
                MMA16816(acc[2 * g],          al0, bh[g][0], bh[g][2]);
                MMA16816(acc[2 * g + 1],      al0, bh[g][1], bh[g][3]);
                MMA16816(acc[10 + 2 * g],     al1, bh[g][0], bh[g][2]);
                MMA16816(acc[10 + 2 * g + 1], al1, bh[g][1], bh[g][3]);
            }
            #pragma unroll
            for (int g = 0; g < 5; g++) {
                MMA16816(acc[2 * g],          ah0, bl[g][0], bl[g][2]);
                MMA16816(acc[2 * g + 1],      ah0, bl[g][1], bl[g][3]);
                MMA16816(acc[10 + 2 * g],     ah1, bl[g][0], bl[g][2]);
                MMA16816(acc[10 + 2 * g + 1], ah1, bl[g][1], bl[g][3]);
            }
        }
    }

    // ---- epilogue ----
    __syncthreads();
    float* ssum = reinterpret_cast<float*>(smem);       // 80
    float* ssq  = ssum + 80;                            // 80
    for (int i = tid; i < 160; i += 128) ssum[i] = 0.f;
    __syncthreads();

    int cb = n0 + (lane & 3) * 2;
    #pragma unroll
    for (int mi = 0; mi < 2; mi++) {
        int r0 = m0 + wid * 32 + mi * 16 + (lane >> 2);
        #pragma unroll
        for (int nt = 0; nt < 10; nt++) {
            float* a4 = acc[mi * 10 + nt];
            int n = cb + nt * 8;
            float bz0 = bias[n], bz1 = bias[n + 1];
            float v00 = a4[0] + bz0, v01 = a4[1] + bz1;
            float v10 = a4[2] + bz0, v11 = a4[3] + bz1;

            if (EPI == 0) {
                __nv_bfloat162 h0, l0, h1, l1;
                split_bf16(v00, h0.x, l0.x); split_bf16(v01, h0.y, l0.y);
                split_bf16(v10, h1.x, l1.x); split_bf16(v11, h1.y, l1.y);
                *reinterpret_cast<__nv_bfloat162*>(Zh + (size_t)r0 * KP2 + n) = h0;
                *reinterpret_cast<__nv_bfloat162*>(Zl + (size_t)r0 * KP2 + n) = l0;
                *reinterpret_cast<__nv_bfloat162*>(Zh + (size_t)(r0 + 8) * KP2 + n) = h1;
                *reinterpret_cast<__nv_bfloat162*>(Zl + (size_t)(r0 + 8) * KP2 + n) = l1;
            }

            float s0 = v00 + v10, q0 = v00 * v00 + v10 * v10;
            float s1 = v01 + v11, q1 = v01 * v01 + v11 * v11;
            #pragma unroll
            for (int off = 16; off >= 4; off >>= 1) {
                s0 += __shfl_down_sync(0xFFFFFFFF, s0, off);
                q0 += __shfl_down_sync(0xFFFFFFFF, q0, off);
                s1 += __shfl_down_sync(0xFFFFFFFF, s1, off);
                q1 += __shfl_down_sync(0xFFFFFFFF, q1, off);
            }
            if (lane < 4) {
                int lc = lane * 2 + nt * 8;
                atomicAdd(&ssum[lc],     s0);
                atomicAdd(&ssum[lc + 1], s1);
                atomicAdd(&ssq[lc],      q0);
                atomicAdd(&ssq[lc + 1],  q1);
            }
        }
    }

    if (EPI == 0 && n0 == 320) {
        for (int i = tid; i < 512; i += 128) {
            int row = i >> 2, q = i & 3;
            size_t off = (size_t)(m0 + row) * KP2 + 400 + q * 4;
            *reinterpret_cast<uint2*>(Zh + off) = make_uint2(0u, 0u);
            *reinterpret_cast<uint2*>(Zl + off) = make_uint2(0u, 0u);
        }
    }

    __syncthreads();
    for (int i = tid; i < 80; i += 128) {
        atomicAdd(&gsum[n0 + i], ssum[i]);
        atomicAdd(&gsq[n0 + i],  ssq[i]);
    }
}

// ---------------- w-vector build: w[k] = sum_j a2_j * W2'[j,k]; D scalar -----
__global__ void __launch_bounds__(256) wvec_kernel(
    const __nv_bfloat16* __restrict__ W2h, const __nv_bfloat16* __restrict__ W2l,
    const float* __restrict__ c2, const float* __restrict__ stats,
    const float* __restrict__ g2, const float* __restrict__ be2,
    float* __restrict__ wD)
{
    __shared__ float a_s[NH];
    __shared__ float part[8][32];
    __shared__ float redD[8];
    int t = threadIdx.x;
    int lane32 = t & 31, slice = t >> 5;

    float dpart = 0.f;
    for (int j = t; j < NH; j += 256) {
        float mean = stats[2 * NH + j] * (1.f / N_ROWS);
        float var  = stats[3 * NH + j] * (1.f / N_ROWS) - mean * mean;
        float a = g2[j] * rsqrtf(var + EPS);
        a_s[j] = a;
        dpart += (be2[j] - a * mean) + a * c2[j];
    }
    #pragma unroll
    for (int off = 16; off > 0; off >>= 1)
        dpart += __shfl_down_sync(0xFFFFFFFF, dpart, off);
    if (lane32 == 0) redD[slice] = dpart;
    __syncthreads();
    if (t == 0 && blockIdx.x == 0) {
        float s = 0.f;
        #pragma unroll
        for (int i = 0; i < 8; i++) s += redD[i];
        wD[KP2] = s;
    }

    int k = blockIdx.x * 32 + lane32;
    float acc = 0.f;
    for (int j = slice * 50; j < slice * 50 + 50; j++)
        acc += a_s[j] * (__bfloat162float(W2h[(size_t)j * KP2 + k])
                       + __bfloat162float(W2l[(size_t)j * KP2 + k]));
    part[slice][lane32] = acc;
    __syncthreads();
    if (slice == 0) {
        float s = 0.f;
        #pragma unroll
        for (int i = 0; i < 8; i++) s += part[i][lane32];
        wD[k] = s;
    }
}

// ---------------- final GEMV: out[n] += sum_k (Z1h+Z1l)[n,k]*w[k] + D --------
__global__ void __launch_bounds__(256) rowdot_kernel(
    const __nv_bfloat16* __restrict__ Zh, const __nv_bfloat16* __restrict__ Zl,
    const float* __restrict__ wD, float* __restrict__ out)
{
    __shared__ float w_s[KP2];
    __shared__ float Ds;
    int t = threadIdx.x;
    for (int k = t; k < KP2; k += 256) w_s[k] = wD[k];
    if (t == 0) Ds = wD[KP2];
    __syncthreads();

    int lane = t & 31, w = t >> 5;
    int row = blockIdx.x * 8 + w;
    const __nv_bfloat162* zh2 = reinterpret_cast<const __nv_bfloat162*>(
        Zh + (size_t)row * KP2);
    const __nv_bfloat162* zl2 = reinterpret_cast<const __nv_bfloat162*>(
        Zl + (size_t)row * KP2);
    float acc = 0.f;
    for (int p = lane; p < KP2 / 2; p += 32) {
        __nv_bfloat162 h2 = zh2[p];
        __nv_bfloat162 l2 = zl2[p];
        float z0 = __bfloat162float(h2.x) + __bfloat162float(l2.x);
        float z1 = __bfloat162float(h2.y) + __bfloat162float(l2.y);
        acc += z0 * w_s[2 * p] + z1 * w_s[2 * p + 1];
    }
    #pragma unroll
    for (int off = 16; off > 0; off >>= 1)
        acc += __shfl_down_sync(0xFFFFFFFF, acc, off);
    if (lane == 0)
        out[row] += acc + Ds;
}

// ---------------- launch ----------------
extern "C" void kernel_launch(void* const* d_in, const int* in_sizes, int n_in,
                              void* d_out, int out_size)
{
    const int*   xi   = (const int*)  d_in[0];
    const float* xv   = (const float*)d_in[1];
    const float* emb1 = (const float*)d_in[2];
    const float* emb2 = (const float*)d_in[3];
    const float* W1   = (const float*)d_in[4];
    const float* b1   = (const float*)d_in[5];
    const float* g1   = (const float*)d_in[6];
    const float* be1  = (const float*)d_in[7];
    const float* W2   = (const float*)d_in[8];
    const float* b2   = (const float*)d_in[9];
    const float* g2   = (const float*)d_in[10];
    const float* be2  = (const float*)d_in[11];
    const float* bias = (const float*)d_in[12];
    float* out = (float*)d_out;

    __nv_bfloat16 *A1h, *A1l, *Z1h, *Z1l, *W1h, *W1l, *W2h, *W2l;
    float *stats, *c2, *wD;
    cudaGetSymbolAddress((void**)&A1h, g_A1h);
    cudaGetSymbolAddress((void**)&A1l, g_A1l);
    cudaGetSymbolAddress((void**)&Z1h, g_Z1h);
    cudaGetSymbolAddress((void**)&Z1l, g_Z1l);
    cudaGetSymbolAddress((void**)&W1h, g_W1h);
    cudaGetSymbolAddress((void**)&W1l, g_W1l);
    cudaGetSymbolAddress((void**)&W2h, g_W2h);
    cudaGetSymbolAddress((void**)&W2l, g_W2l);
    cudaGetSymbolAddress((void**)&stats, g_stats);
    cudaGetSymbolAddress((void**)&c2,    g_c2);
    cudaGetSymbolAddress((void**)&wD,    g_w);

    const int SMEM_BYTES = 2 * 16640 * 2;   // 66560
    cudaFuncSetAttribute(hmma_gemm_kernel<0>,
                         cudaFuncAttributeMaxDynamicSharedMemorySize, SMEM_BYTES);
    cudaFuncSetAttribute(hmma_gemm_kernel<1>,
                         cudaFuncAttributeMaxDynamicSharedMemorySize, SMEM_BYTES);

    embed_kernel<<<N_ROWS, 128>>>(xi, xv, emb1, emb2, bias, W1,
                                  A1h, A1l, W1h, W1l, out, stats);

    dim3 ggrid(5, N_ROWS / 128);
    hmma_gemm_kernel<0><<<ggrid, 128, SMEM_BYTES>>>(
        A1h, A1l, W1h, W1l, b1, Z1h, Z1l,
        stats, stats + NH, KP1, NC1);

    repackW2c_kernel<<<NH / 4, 256>>>(W2, b2, stats, g1, be1, W2h, W2l, c2);

    hmma_gemm_kernel<1><<<ggrid, 128, SMEM_BYTES>>>(
        Z1h, Z1l, W2h, W2l, c2, nullptr, nullptr,
        stats + 2 * NH, stats + 3 * NH, KP2, NC2);

    wvec_kernel<<<13, 256>>>(W2h, W2l, c2, stats, g2, be2, wD);
    rowdot_kernel<<<N_ROWS / 8, 256>>>(Z1h, Z1l, wD, out);
}